// round 7
// baseline (speedup 1.0000x reference)
#include <cuda_runtime.h>
#include <cuda_bf16.h>

// Problem constants (B=32, S=1024, V=64, H=4096)
#define VOCAB   64
#define HID     4096
#define UOUT    128          // 2*V
#define NBLK    128          // H-split blocks
#define HCHUNK  (HID / NBLK) // 32
#define NROWS   (32 * 1024)  // 32768

// Per-token output index table: out_idx[t] = (scale_idx[t]*t + loc_idx[t]) mod 64
__device__ int    g_table[VOCAB];
// Per-row token index, extracted during K1
__device__ int    g_tok[NROWS];                         // 128 KB
// Partial logits scratch: part[t][b][uq], float4 u-quads
__device__ float4 g_part[VOCAB * NBLK * (UOUT / 4)];    // 4 MB

union F2u { unsigned long long u; float2 f; };

// Packed dual-FMA: d = a*b + d on two fp32 lanes.
__device__ __forceinline__ void ffma2(unsigned long long& d,
                                      const unsigned long long a,
                                      const unsigned long long b) {
    asm("fma.rn.f32x2 %0, %1, %2, %3;" : "=l"(d) : "l"(a), "l"(b), "l"(d));
}

// ---------------------------------------------------------------------------
// K1: partial logits + token extraction (fills the idle memory pipe).
// Order: staging LDGs issued -> extraction (64 KB read, decode, g_tok store;
// its latency covers the staging loads) -> smem commit -> FFMA2 compute ->
// partial stores. Block b owns H-chunk [b*32, b*32+32) and rows
// [b*256, b*256+256). 512 threads.
// ---------------------------------------------------------------------------
__global__ __launch_bounds__(512, 1)
void partial_kernel(const float* __restrict__ W1, const float* __restrict__ b1,
                    const float* __restrict__ W2, const float4* __restrict__ in) {
    __shared__ float4 nets2[VOCAB * (HCHUNK / 2)];   // 16 KB [t][hb] dup {n,n,n',n'}
    __shared__ float4 w2s  [HCHUNK * (UOUT / 4)];    // 16 KB [h][uq]

    const int b   = blockIdx.x;
    const int tid = threadIdx.x;
    const int h0  = b * HCHUNK;

    // --- staging LDGs first ---
    const int jt = tid >> 3;           // token 0..63
    const int jf = tid & 7;            // float4 within h-chunk
    const float4 w1v = *reinterpret_cast<const float4*>(W1 + jt * HID + h0 + jf * 4);
    const float4 b1v = *reinterpret_cast<const float4*>(b1 + h0 + jf * 4);
    const float4* __restrict__ w2src = reinterpret_cast<const float4*>(W2 + h0 * UOUT);
    const float4 w2a = w2src[tid];
    const float4 w2b = w2src[tid + 512];

    // --- token extraction for rows [b*256, b*256+256) (overlaps staging) ---
    {
        const float4* src = in + b * 4096;
        float4 v[8];
        #pragma unroll
        for (int i = 0; i < 8; ++i) v[i] = src[tid + i * 512];
        #pragma unroll
        for (int i = 0; i < 8; ++i) {
            const int k = tid + i * 512;
            const int q = k & 15;
            int cand = -1;
            if (v[i].x > 0.5f) cand = q * 4 + 0;
            if (v[i].y > 0.5f) cand = q * 4 + 1;
            if (v[i].z > 0.5f) cand = q * 4 + 2;
            if (v[i].w > 0.5f) cand = q * 4 + 3;
            if (cand >= 0) g_tok[b * 256 + (k >> 4)] = cand;
        }
    }

    // --- commit staging to smem ---
    {
        float n0 = fmaxf(w1v.x + b1v.x, 0.f);
        float n1 = fmaxf(w1v.y + b1v.y, 0.f);
        float n2 = fmaxf(w1v.z + b1v.z, 0.f);
        float n3 = fmaxf(w1v.w + b1v.w, 0.f);
        nets2[jt * 16 + jf * 2 + 0] = make_float4(n0, n0, n1, n1);
        nets2[jt * 16 + jf * 2 + 1] = make_float4(n2, n2, n3, n3);
        w2s[tid]       = w2a;
        w2s[tid + 512] = w2b;
    }
    __syncthreads();

    // --- FFMA2 compute: 4 tokens x 4 u per thread ---
    const int uq = tid & 31;
    const int t0 = (tid >> 5) * 4;

    const ulonglong2* __restrict__ n2v = reinterpret_cast<const ulonglong2*>(nets2);
    const ulonglong2* __restrict__ w2v = reinterpret_cast<const ulonglong2*>(w2s);

    unsigned long long acc[4][2];
    #pragma unroll
    for (int t = 0; t < 4; ++t) { acc[t][0] = 0ull; acc[t][1] = 0ull; }

    #pragma unroll
    for (int hb = 0; hb < HCHUNK / 2; ++hb) {              // 2 h per step
        const ulonglong2 w0 = w2v[(2 * hb)     * 32 + uq];
        const ulonglong2 w1 = w2v[(2 * hb + 1) * 32 + uq];
        #pragma unroll
        for (int t = 0; t < 4; ++t) {
            const ulonglong2 nn = n2v[(t0 + t) * 16 + hb]; // broadcast
            ffma2(acc[t][0], nn.x, w0.x);
            ffma2(acc[t][1], nn.x, w0.y);
            ffma2(acc[t][0], nn.y, w1.x);
            ffma2(acc[t][1], nn.y, w1.y);
        }
    }

    #pragma unroll
    for (int t = 0; t < 4; ++t) {
        F2u a0, a1; a0.u = acc[t][0]; a1.u = acc[t][1];
        g_part[((t0 + t) * NBLK + b) * 32 + uq] =
            make_float4(a0.f.x, a0.f.y, a1.f.x, a1.f.y);
    }
}

// ---------------------------------------------------------------------------
// K2: reduce partials over the 128 H-blocks, add b2, argmax both halves.
// One block per token, 256 threads (8 warps x 16 b's each).
// ---------------------------------------------------------------------------
__global__ __launch_bounds__(256, 1)
void reduce_kernel(const float* __restrict__ b2) {
    __shared__ float red[8][UOUT];
    __shared__ float logits[UOUT];

    const int t    = blockIdx.x;
    const int tid  = threadIdx.x;
    const int warp = tid >> 5;
    const int lane = tid & 31;

    float4 acc = make_float4(0.f, 0.f, 0.f, 0.f);
    const float4* base = &g_part[(t * NBLK) * 32 + lane];
    #pragma unroll 8
    for (int b = warp * 16; b < warp * 16 + 16; ++b) {
        const float4 v = base[b * 32];
        acc.x += v.x; acc.y += v.y; acc.z += v.z; acc.w += v.w;
    }
    red[warp][lane * 4 + 0] = acc.x;
    red[warp][lane * 4 + 1] = acc.y;
    red[warp][lane * 4 + 2] = acc.z;
    red[warp][lane * 4 + 3] = acc.w;
    __syncthreads();

    if (tid < UOUT) {
        float s = b2[tid];
        #pragma unroll
        for (int w = 0; w < 8; ++w) s += red[w][tid];
        logits[tid] = s;
    }
    __syncthreads();

    if (tid == 0) {
        // jnp.argmax keeps the FIRST max -> strict '>' comparison.
        int   li = 0; float lm = logits[0];
        #pragma unroll
        for (int k = 1; k < VOCAB; ++k) if (logits[k] > lm) { lm = logits[k]; li = k; }
        int   si = 0; float sm = logits[VOCAB];
        #pragma unroll
        for (int k = 1; k < VOCAB; ++k) if (logits[VOCAB + k] > sm) { sm = logits[VOCAB + k]; si = k; }
        // loc = first half, scale = second half (jnp.split order)
        g_table[t] = (si * t + li) & (VOCAB - 1);
    }
}

// ---------------------------------------------------------------------------
// K3: pure writer. Each thread writes 4 output float4s; per row it reads the
// precomputed token (16-lane broadcast LDG) and the 64-entry table (L1-hot).
// 8 MB coalesced stores, ~0.13 MB loads.
// ---------------------------------------------------------------------------
#define TOTAL_F4 (32 * 1024 * 64 / 4)   // 524288
#define SC_STRIDE (TOTAL_F4 / 4)        // 131072 (multiple of 16 -> same q per k)

__global__ __launch_bounds__(256)
void write_kernel(float4* __restrict__ out) {
    const int base = blockIdx.x * 256 + threadIdx.x;
    const int q    = base & 15;

    int tok[4];
    #pragma unroll
    for (int k = 0; k < 4; ++k) tok[k] = g_tok[(base + k * SC_STRIDE) >> 4];

    #pragma unroll
    for (int k = 0; k < 4; ++k) {
        const int oi = g_table[tok[k]];
        float4 o = make_float4(0.f, 0.f, 0.f, 0.f);
        if ((oi >> 2) == q) reinterpret_cast<float*>(&o)[oi & 3] = 1.0f;
        out[base + k * SC_STRIDE] = o;
    }
}

// ---------------------------------------------------------------------------
extern "C" void kernel_launch(void* const* d_in, const int* in_sizes, int n_in,
                              void* d_out, int out_size) {
    const float* inputs = nullptr;
    const float* W1 = nullptr;
    const float* b1 = nullptr;
    const float* W2 = nullptr;
    const float* b2 = nullptr;

    for (int i = 0; i < n_in; ++i) {
        switch (in_sizes[i]) {
            case 32 * 1024 * 64: inputs = (const float*)d_in[i]; break; // 2097152
            case 64 * 4096:      W1     = (const float*)d_in[i]; break; // 262144
            case 4096:           b1     = (const float*)d_in[i]; break;
            case 4096 * 128:     W2     = (const float*)d_in[i]; break; // 524288
            case 128:            b2     = (const float*)d_in[i]; break;
            default: break;
        }
    }

    partial_kernel<<<NBLK, 512>>>(W1, b1, W2,
                                  reinterpret_cast<const float4*>(inputs));
    reduce_kernel<<<VOCAB, 256>>>(b2);
    write_kernel<<<SC_STRIDE / 256, 256>>>(reinterpret_cast<float4*>(d_out));
}